// round 15
// baseline (speedup 1.0000x reference)
#include <cuda_runtime.h>

// ---------------------------------------------------------------------------
// GeodesicSpectralModel, round 14:
//  - packed f32x2 Gamma/Euler machinery (round 13) kept;
//  - occupancy fix: uniform flow-MLP weights moved to shared memory and
//    __launch_bounds__(128, 4) -> <=128 regs, 4 blocks/SM (latency coverage);
//  - shooting compressed further: 2 exact Newton iterations + secant closure
//    of the remaining 8 -> 3 trajectory integrations total (was 4).
// ---------------------------------------------------------------------------

namespace {
constexpr int HM = 8;
constexpr int HS = 16;
constexpr int NC = 20;   // Chebyshev order in c
constexpr int NL = 12;   // Chebyshev order in lam
}

#define DT 0.1f
#define LOG2E_F 1.4426950408889634f
#define TWO_LOG2E_F 2.8853900817779268f
#define LN2_F 0.6931471805599453f
#define PI_F 3.14159265358979f
// c domain [-1.5, 2.5]
#define C_CENTER 0.5f
#define C_HALFW  2.0f
#define INV_HALFW 0.5f
// lam domain [0, 1]
#define L_CENTER 0.5f
#define L_HALFW  0.5f

__device__ float gD2[NC * NL];   // derivative coeffs, pre-scaled by 0.5*INV_HALFW

// ---------------- packed f32x2 primitives ----------------
typedef unsigned long long f2;
__device__ __forceinline__ f2 pk2(float lo, float hi) {
    f2 r; asm("mov.b64 %0, {%1, %2};" : "=l"(r) : "f"(lo), "f"(hi)); return r;
}
__device__ __forceinline__ void upk2(float& lo, float& hi, f2 v) {
    asm("mov.b64 {%0, %1}, %2;" : "=f"(lo), "=f"(hi) : "l"(v));
}
__device__ __forceinline__ f2 fma2_(f2 a, f2 b, f2 c) {
    f2 r; asm("fma.rn.f32x2 %0, %1, %2, %3;" : "=l"(r) : "l"(a), "l"(b), "l"(c)); return r;
}
__device__ __forceinline__ f2 add2_(f2 a, f2 b) {
    f2 r; asm("add.rn.f32x2 %0, %1, %2;" : "=l"(r) : "l"(a), "l"(b)); return r;
}
__device__ __forceinline__ f2 mul2_(f2 a, f2 b) {
    f2 r; asm("mul.rn.f32x2 %0, %1, %2;" : "=l"(r) : "l"(a), "l"(b)); return r;
}

// ---------------- scalar MUFU helpers ----------------
__device__ __forceinline__ float f_ex2(float x) {
    float r; asm("ex2.approx.f32 %0, %1;" : "=f"(r) : "f"(x)); return r;
}
__device__ __forceinline__ float f_lg2(float x) {
    float r; asm("lg2.approx.f32 %0, %1;" : "=f"(r) : "f"(x)); return r;
}
__device__ __forceinline__ float f_rcp(float x) {
    float r; asm("rcp.approx.f32 %0, %1;" : "=f"(r) : "f"(x)); return r;
}
__device__ __forceinline__ float tanh_fast(float x) {
    float e = f_ex2(x * TWO_LOG2E_F);
    return fmaf(-2.0f, f_rcp(e + 1.0f), 1.0f);
}
__device__ __forceinline__ float tanh_pre(float a) {   // arg pre-scaled by 2*log2e
    float e = f_ex2(a);
    return fmaf(-2.0f, f_rcp(e + 1.0f), 1.0f);
}

struct SharedW {
    float w1[HM];
    float W2[HM * HM];
    float b2[HM];
    float W3[HM];
    float b3;
};

__device__ __forceinline__ float metric_eval(float c, const SharedW& s,
                                             const float (&b1p)[HM]) {
    float h1[HM];
#pragma unroll
    for (int j = 0; j < HM; j++)
        h1[j] = tanh_fast(fmaf(c, s.w1[j], b1p[j]));
    float o = s.b3;
#pragma unroll
    for (int j = 0; j < HM; j++) {
        float a = s.b2[j];
#pragma unroll
        for (int i = 0; i < HM; i++)
            a = fmaf(h1[i], s.W2[i * HM + j], a);
        o = fmaf(tanh_fast(a), s.W3[j], o);
    }
    float ax = fabsf(o);
    float em = f_ex2(-ax * LOG2E_F);
    float sp = fmaxf(o, 0.0f) + LN2_F * f_lg2(1.0f + em);
    return sp + 1e-6f;
}

// ---------------------------------------------------------------------------
// Setup kernel (unchanged).
// ---------------------------------------------------------------------------
__global__ void __launch_bounds__(384) setup_kernel(
    const float* __restrict__ mW1, const float* __restrict__ mb1,
    const float* __restrict__ mW2, const float* __restrict__ mb2,
    const float* __restrict__ mW3, const float* __restrict__ mb3)
{
    __shared__ float fS[NC][NL];
    __shared__ float TcS[NC][NC];
    __shared__ float TlS[NL][NL];
    __shared__ float PS[NC][NL];
    __shared__ float A2S[NC][NL];

    int tid = threadIdx.x;

    SharedW s;
#pragma unroll
    for (int j = 0; j < HM; j++) {
        s.w1[j] = mW1[j];
        s.b2[j] = mb2[j];
        s.W3[j] = mW3[j];
    }
#pragma unroll
    for (int k = 0; k < HM * HM; k++) s.W2[k] = mW2[k];
    s.b3 = mb3[0];

    if (tid < NC * NL) {
        int n = tid / NL, m = tid % NL;
        float x = __cosf(PI_F * ((float)n + 0.5f) / (float)NC);
        float u = __cosf(PI_F * ((float)m + 0.5f) / (float)NL);
        float c   = fmaf(x, C_HALFW, C_CENTER);
        float lam = fmaf(u, L_HALFW, L_CENTER);
        float b1p[HM];
#pragma unroll
        for (int j = 0; j < HM; j++)
            b1p[j] = fmaf(lam, mW1[HM + j], mb1[j]);
        float g = metric_eval(c, s, b1p);
        fS[n][m] = LN2_F * f_lg2(g);
    }
    if (tid < NC) {
        int n = tid;
        float x = __cosf(PI_F * ((float)n + 0.5f) / (float)NC);
        float t0 = 1.0f, t1 = x, x2 = 2.0f * x;
        TcS[0][n] = 1.0f;
        TcS[1][n] = x;
#pragma unroll
        for (int k = 2; k < NC; k++) {
            float t = fmaf(x2, t1, -t0);
            TcS[k][n] = t;
            t0 = t1; t1 = t;
        }
    }
    if (tid < NL) {
        int m = tid;
        float u = __cosf(PI_F * ((float)m + 0.5f) / (float)NL);
        float t0 = 1.0f, t1 = u, u2 = 2.0f * u;
        TlS[0][m] = 1.0f;
        TlS[1][m] = u;
#pragma unroll
        for (int j = 2; j < NL; j++) {
            float t = fmaf(u2, t1, -t0);
            TlS[j][m] = t;
            t0 = t1; t1 = t;
        }
    }
    __syncthreads();

    if (tid < NC * NL) {
        int n = tid / NL, j = tid % NL;
        float acc = 0.0f;
#pragma unroll
        for (int m = 0; m < NL; m++)
            acc = fmaf(fS[n][m], TlS[j][m], acc);
        PS[n][j] = acc;
    }
    __syncthreads();

    if (tid < NC * NL) {
        int k = tid / NL, j = tid % NL;
        float acc = 0.0f;
#pragma unroll
        for (int n = 0; n < NC; n++)
            acc = fmaf(TcS[k][n], PS[n][j], acc);
        acc *= (2.0f / (float)NC) * (2.0f / (float)NL);
        if (j == 0) acc *= 0.5f;
        A2S[k][j] = acc;
    }
    __syncthreads();

    if (tid < NL) {
        int j = tid;
        float D[NC];
        D[NC - 1] = 0.0f;
        D[NC - 2] = (2.0f * (float)(NC - 1)) * A2S[NC - 1][j];
#pragma unroll
        for (int k = NC - 3; k >= 0; --k)
            D[k] = fmaf(2.0f * (float)(k + 1), A2S[k + 1][j], D[k + 2]);
#pragma unroll
        for (int k = 0; k < NC; k++)
            gD2[k * NL + j] = D[k] * (0.5f * INV_HALFW);
    }
}

// ---------------------------------------------------------------------------
// Packed Gamma: even/odd split Clenshaw (round 13).
// ---------------------------------------------------------------------------
__device__ __forceinline__ f2 gamma2(f2 c2, const f2 (&D)[NC], f2 h0,
                                     f2 invhP, f2 coffP, f2 m1P) {
    f2 yP = fma2_(c2, invhP, coffP);
    f2 tw = add2_(yP, yP);
    f2 zP = fma2_(tw, yP, m1P);        // z = 2y^2 - 1
    f2 z2P = add2_(zP, zP);
    f2 e1 = 0ULL, e2 = 0ULL;
#pragma unroll
    for (int m = 9; m >= 1; --m) {
        f2 u = fma2_(z2P, e1, fma2_(e2, m1P, D[2 * m]));
        e2 = e1; e1 = u;
    }
    f2 Se = fma2_(zP, e1, fma2_(e2, m1P, h0));        // h0 = 0.5*D[0] pair
    f2 o1 = 0ULL, o2 = 0ULL;
#pragma unroll
    for (int m = 8; m >= 1; --m) {
        f2 u = fma2_(z2P, o1, fma2_(o2, m1P, D[2 * m + 1]));
        o2 = o1; o1 = u;
    }
    f2 w1P = add2_(z2P, m1P);                         // W_1(z) = 2z - 1
    f2 So = fma2_(w1P, o1, fma2_(o2, m1P, D[1]));
    return fma2_(yP, So, Se);
}

// 10 packed Euler steps, returning final c pair (shooting probe).
__device__ __forceinline__ f2 integrate_c2(f2 cs2, f2 v2, const f2 (&D)[NC],
                                           f2 h0, f2 invhP, f2 coffP, f2 m1P,
                                           f2 dtP, f2 mdtP) {
    f2 c2 = cs2, vv2 = v2;
#pragma unroll 1
    for (int k = 0; k < 10; ++k) {
        f2 g2 = gamma2(c2, D, h0, invhP, coffP, m1P);
        f2 cn = fma2_(vv2, dtP, c2);
        f2 t = mul2_(g2, vv2);
        t = mul2_(t, vv2);
        vv2 = fma2_(t, mdtP, vv2);
        c2 = cn;
    }
    return c2;
}

// ---------------------------------------------------------------------------
// Main kernel: 2 elements per thread, packed; 4 blocks/SM.
// ---------------------------------------------------------------------------
__global__ void __launch_bounds__(128, 4) geo_main_kernel(
    const float* __restrict__ c_source, const float* __restrict__ c_target,
    const float* __restrict__ lamv, const float* __restrict__ A_source,
    const float* __restrict__ sW1, const float* __restrict__ sb1,
    const float* __restrict__ sW2, const float* __restrict__ sb2,
    float* __restrict__ out, int n, int half)
{
    __shared__ f2 D2dup[NC * NL];     // coefficients duplicated into both lanes
    __shared__ float fwc[HS], fwv[HS], fwA[HS], fwo[HS];  // uniform flow weights
    for (int k = threadIdx.x; k < NC * NL; k += blockDim.x) {
        float w = gD2[k];
        D2dup[k] = pk2(w, w);
    }
    if (threadIdx.x < HS) {
        int j = threadIdx.x;
        fwc[j] = sW1[j] * TWO_LOG2E_F;
        fwv[j] = sW1[HS + j] * TWO_LOG2E_F;
        fwA[j] = sW1[3 * HS + j] * TWO_LOG2E_F;
        fwo[j] = sW2[j];
    }
    __syncthreads();

    int t = blockIdx.x * blockDim.x + threadIdx.x;
    if (t >= half) return;
    int i0 = t, i1 = t + half;
    bool has1 = (i1 < n);
    int i1s = has1 ? i1 : i0;

    float cs0 = c_source[i0], ct0 = c_target[i0], lam0 = lamv[i0];
    float cs1 = c_source[i1s], ct1 = c_target[i1s], lam1 = lamv[i1s];

    const f2 m1P   = pk2(-1.0f, -1.0f);
    const f2 dtP   = pk2(DT, DT);
    const f2 mdtP  = pk2(-DT, -DT);
    const f2 invhP = pk2(INV_HALFW, INV_HALFW);
    const f2 coffP = pk2(-C_CENTER * INV_HALFW, -C_CENTER * INV_HALFW);

    // lam Chebyshev basis (packed) + contraction -> packed series Dc
    float yl0 = fminf(fmaxf(fmaf(2.0f, lam0, -1.0f), -1.0f), 1.0f);
    float yl1 = fminf(fmaxf(fmaf(2.0f, lam1, -1.0f), -1.0f), 1.0f);
    f2 ylP = pk2(yl0, yl1);
    f2 y2lP = add2_(ylP, ylP);
    f2 Tl[NL];
    Tl[0] = pk2(1.0f, 1.0f);
    Tl[1] = ylP;
#pragma unroll
    for (int j = 2; j < NL; j++)
        Tl[j] = fma2_(y2lP, Tl[j - 1], mul2_(Tl[j - 2], m1P));

    f2 Dc[NC];
#pragma unroll
    for (int k = 0; k < NC; k++) {
        f2 acc = D2dup[k * NL];        // Tl[0] == 1
#pragma unroll
        for (int j = 1; j < NL; j++)
            acc = fma2_(D2dup[k * NL + j], Tl[j], acc);
        Dc[k] = acc;
    }
    f2 h0 = mul2_(Dc[0], pk2(0.5f, 0.5f));

    // ---- shooting: 2 exact Newton iterations + secant closure of 8 ----
    float v0 = ct0 - cs0, v1 = ct1 - cs1;
    f2 cs2 = pk2(cs0, cs1);
    float va0 = 0.f, ra0 = 0.f, vb0 = 0.f, rb0 = 0.f;
    float va1 = 0.f, ra1 = 0.f, vb1 = 0.f, rb1 = 0.f;
#pragma unroll 1
    for (int it = 0; it < 2; ++it) {
        f2 cf2 = integrate_c2(cs2, pk2(v0, v1), Dc, h0, invhP, coffP, m1P, dtP, mdtP);
        float cf0, cf1;
        upk2(cf0, cf1, cf2);
        float r0 = cf0 - ct0, r1 = cf1 - ct1;
        if (it == 0) { va0 = v0; ra0 = r0; va1 = v1; ra1 = r1; }
        if (it == 1) { vb0 = v0; rb0 = r0; vb1 = v1; rb1 = r1; }
        v0 = v0 - 0.5f * r0;
        v1 = v1 - 0.5f * r1;
    }
    // v = v2.  Model iterations 2..9: r_k = q^{k-1} r1, so
    // v10 = v2 - 0.5 * r1 * q * (1 + q + ... + q^7).
    {
        float db = vb0 - va0;
        float beta = (fabsf(db) > 1e-12f) ? __fdividef(rb0 - ra0, db) : 1.0f;
        float q = fminf(fmaxf(1.0f - 0.5f * beta, 0.0f), 0.9f);
        float S = 1.0f;
#pragma unroll
        for (int j = 0; j < 7; j++) S = fmaf(q, S, 1.0f);   // 1+q+...+q^7
        v0 = v0 - 0.5f * rb0 * q * S;
    }
    {
        float db = vb1 - va1;
        float beta = (fabsf(db) > 1e-12f) ? __fdividef(rb1 - ra1, db) : 1.0f;
        float q = fminf(fmaxf(1.0f - 0.5f * beta, 0.0f), 0.9f);
        float S = 1.0f;
#pragma unroll
        for (int j = 0; j < 7; j++) S = fmaf(q, S, 1.0f);
        v1 = v1 - 0.5f * rb1 * q * S;
    }

    // ---- final integrate: packed Gamma/steps + scalar x2 flow MLP ----
    // per-element lam-folded biases stay in registers; uniform weights in smem
    float sbp0[HS], sbp1[HS];
#pragma unroll
    for (int j = 0; j < HS; j++) {
        sbp0[j] = fmaf(lam0, sW1[2 * HS + j], sb1[j]) * TWO_LOG2E_F;
        sbp1[j] = fmaf(lam1, sW1[2 * HS + j], sb1[j]) * TWO_LOG2E_F;
    }
    float sb2s = sb2[0];

    float A0 = A_source[i0], A1 = A_source[i1s];
    f2 c2 = cs2;
    f2 v2 = pk2(v0, v1);
#pragma unroll 1
    for (int k = 0; k < 10; ++k) {
        f2 g2 = gamma2(c2, Dc, h0, invhP, coffP, m1P);
        float cc0, cc1, vv0, vv1;
        upk2(cc0, cc1, c2);
        upk2(vv0, vv1, v2);
        float acc0 = sb2s, acc1 = sb2s;
#pragma unroll
        for (int j = 0; j < HS; j++) {
            float wc = fwc[j], wv = fwv[j], wA = fwA[j], wo = fwo[j];
            float a0 = fmaf(cc0, wc, sbp0[j]);
            a0 = fmaf(vv0, wv, a0);
            a0 = fmaf(A0, wA, a0);
            acc0 = fmaf(tanh_pre(a0), wo, acc0);
            float a1 = fmaf(cc1, wc, sbp1[j]);
            a1 = fmaf(vv1, wv, a1);
            a1 = fmaf(A1, wA, a1);
            acc1 = fmaf(tanh_pre(a1), wo, acc1);
        }
        c2 = fma2_(v2, dtP, c2);
        f2 tt = mul2_(g2, v2);
        tt = mul2_(tt, v2);
        v2 = fma2_(tt, mdtP, v2);
        A0 = fmaf(acc0, DT, A0);
        A1 = fmaf(acc1, DT, A1);
    }
    out[i0] = A0;
    if (has1) out[i1] = A1;
}

extern "C" void kernel_launch(void* const* d_in, const int* in_sizes, int n_in,
                              void* d_out, int out_size)
{
    const float* c_source = (const float*)d_in[0];
    const float* c_target = (const float*)d_in[1];
    const float* lam      = (const float*)d_in[2];
    const float* A_source = (const float*)d_in[3];
    const float* mW1 = (const float*)d_in[4];
    const float* mb1 = (const float*)d_in[5];
    const float* mW2 = (const float*)d_in[6];
    const float* mb2 = (const float*)d_in[7];
    const float* mW3 = (const float*)d_in[8];
    const float* mb3 = (const float*)d_in[9];
    const float* sW1 = (const float*)d_in[10];
    const float* sb1 = (const float*)d_in[11];
    const float* sW2 = (const float*)d_in[12];
    const float* sb2 = (const float*)d_in[13];
    float* out = (float*)d_out;

    int n = in_sizes[0];
    int half = (n + 1) / 2;
    int block = 128;
    int grid = (half + block - 1) / block;

    setup_kernel<<<1, 384>>>(mW1, mb1, mW2, mb2, mW3, mb3);
    geo_main_kernel<<<grid, block>>>(c_source, c_target, lam, A_source,
                                     sW1, sb1, sW2, sb2, out, n, half);
}

// round 16
// speedup vs baseline: 1.7647x; 1.7647x over previous
#include <cuda_runtime.h>

// ---------------------------------------------------------------------------
// GeodesicSpectralModel, round 16 = round 13 base + validated wins of R15:
//  - packed f32x2 Gamma/Euler machinery, 2 elems/thread, launch_bounds(128,3)
//    (NO 4-block reg cap: R15 proved the 128-reg cap spills and regresses);
//  - shooting: 2 exact Newton iterations + secant closure of the remaining 8
//    (validated at rel_err 1.95e-5 in R15) -> 3 trajectory integrations;
//  - uniform flow-MLP weights in shared memory (frees ~64 regs).
// ---------------------------------------------------------------------------

namespace {
constexpr int HM = 8;
constexpr int HS = 16;
constexpr int NC = 20;   // Chebyshev order in c
constexpr int NL = 12;   // Chebyshev order in lam
}

#define DT 0.1f
#define LOG2E_F 1.4426950408889634f
#define TWO_LOG2E_F 2.8853900817779268f
#define LN2_F 0.6931471805599453f
#define PI_F 3.14159265358979f
// c domain [-1.5, 2.5]
#define C_CENTER 0.5f
#define C_HALFW  2.0f
#define INV_HALFW 0.5f
// lam domain [0, 1]
#define L_CENTER 0.5f
#define L_HALFW  0.5f

__device__ float gD2[NC * NL];   // derivative coeffs, pre-scaled by 0.5*INV_HALFW

// ---------------- packed f32x2 primitives ----------------
typedef unsigned long long f2;
__device__ __forceinline__ f2 pk2(float lo, float hi) {
    f2 r; asm("mov.b64 %0, {%1, %2};" : "=l"(r) : "f"(lo), "f"(hi)); return r;
}
__device__ __forceinline__ void upk2(float& lo, float& hi, f2 v) {
    asm("mov.b64 {%0, %1}, %2;" : "=f"(lo), "=f"(hi) : "l"(v));
}
__device__ __forceinline__ f2 fma2_(f2 a, f2 b, f2 c) {
    f2 r; asm("fma.rn.f32x2 %0, %1, %2, %3;" : "=l"(r) : "l"(a), "l"(b), "l"(c)); return r;
}
__device__ __forceinline__ f2 add2_(f2 a, f2 b) {
    f2 r; asm("add.rn.f32x2 %0, %1, %2;" : "=l"(r) : "l"(a), "l"(b)); return r;
}
__device__ __forceinline__ f2 mul2_(f2 a, f2 b) {
    f2 r; asm("mul.rn.f32x2 %0, %1, %2;" : "=l"(r) : "l"(a), "l"(b)); return r;
}

// ---------------- scalar MUFU helpers ----------------
__device__ __forceinline__ float f_ex2(float x) {
    float r; asm("ex2.approx.f32 %0, %1;" : "=f"(r) : "f"(x)); return r;
}
__device__ __forceinline__ float f_lg2(float x) {
    float r; asm("lg2.approx.f32 %0, %1;" : "=f"(r) : "f"(x)); return r;
}
__device__ __forceinline__ float f_rcp(float x) {
    float r; asm("rcp.approx.f32 %0, %1;" : "=f"(r) : "f"(x)); return r;
}
__device__ __forceinline__ float tanh_fast(float x) {
    float e = f_ex2(x * TWO_LOG2E_F);
    return fmaf(-2.0f, f_rcp(e + 1.0f), 1.0f);
}
__device__ __forceinline__ float tanh_pre(float a) {   // arg pre-scaled by 2*log2e
    float e = f_ex2(a);
    return fmaf(-2.0f, f_rcp(e + 1.0f), 1.0f);
}

struct SharedW {
    float w1[HM];
    float W2[HM * HM];
    float b2[HM];
    float W3[HM];
    float b3;
};

__device__ __forceinline__ float metric_eval(float c, const SharedW& s,
                                             const float (&b1p)[HM]) {
    float h1[HM];
#pragma unroll
    for (int j = 0; j < HM; j++)
        h1[j] = tanh_fast(fmaf(c, s.w1[j], b1p[j]));
    float o = s.b3;
#pragma unroll
    for (int j = 0; j < HM; j++) {
        float a = s.b2[j];
#pragma unroll
        for (int i = 0; i < HM; i++)
            a = fmaf(h1[i], s.W2[i * HM + j], a);
        o = fmaf(tanh_fast(a), s.W3[j], o);
    }
    float ax = fabsf(o);
    float em = f_ex2(-ax * LOG2E_F);
    float sp = fmaxf(o, 0.0f) + LN2_F * f_lg2(1.0f + em);
    return sp + 1e-6f;
}

// ---------------------------------------------------------------------------
// Setup kernel (unchanged).
// ---------------------------------------------------------------------------
__global__ void __launch_bounds__(384) setup_kernel(
    const float* __restrict__ mW1, const float* __restrict__ mb1,
    const float* __restrict__ mW2, const float* __restrict__ mb2,
    const float* __restrict__ mW3, const float* __restrict__ mb3)
{
    __shared__ float fS[NC][NL];
    __shared__ float TcS[NC][NC];
    __shared__ float TlS[NL][NL];
    __shared__ float PS[NC][NL];
    __shared__ float A2S[NC][NL];

    int tid = threadIdx.x;

    SharedW s;
#pragma unroll
    for (int j = 0; j < HM; j++) {
        s.w1[j] = mW1[j];
        s.b2[j] = mb2[j];
        s.W3[j] = mW3[j];
    }
#pragma unroll
    for (int k = 0; k < HM * HM; k++) s.W2[k] = mW2[k];
    s.b3 = mb3[0];

    if (tid < NC * NL) {
        int n = tid / NL, m = tid % NL;
        float x = __cosf(PI_F * ((float)n + 0.5f) / (float)NC);
        float u = __cosf(PI_F * ((float)m + 0.5f) / (float)NL);
        float c   = fmaf(x, C_HALFW, C_CENTER);
        float lam = fmaf(u, L_HALFW, L_CENTER);
        float b1p[HM];
#pragma unroll
        for (int j = 0; j < HM; j++)
            b1p[j] = fmaf(lam, mW1[HM + j], mb1[j]);
        float g = metric_eval(c, s, b1p);
        fS[n][m] = LN2_F * f_lg2(g);
    }
    if (tid < NC) {
        int n = tid;
        float x = __cosf(PI_F * ((float)n + 0.5f) / (float)NC);
        float t0 = 1.0f, t1 = x, x2 = 2.0f * x;
        TcS[0][n] = 1.0f;
        TcS[1][n] = x;
#pragma unroll
        for (int k = 2; k < NC; k++) {
            float t = fmaf(x2, t1, -t0);
            TcS[k][n] = t;
            t0 = t1; t1 = t;
        }
    }
    if (tid < NL) {
        int m = tid;
        float u = __cosf(PI_F * ((float)m + 0.5f) / (float)NL);
        float t0 = 1.0f, t1 = u, u2 = 2.0f * u;
        TlS[0][m] = 1.0f;
        TlS[1][m] = u;
#pragma unroll
        for (int j = 2; j < NL; j++) {
            float t = fmaf(u2, t1, -t0);
            TlS[j][m] = t;
            t0 = t1; t1 = t;
        }
    }
    __syncthreads();

    if (tid < NC * NL) {
        int n = tid / NL, j = tid % NL;
        float acc = 0.0f;
#pragma unroll
        for (int m = 0; m < NL; m++)
            acc = fmaf(fS[n][m], TlS[j][m], acc);
        PS[n][j] = acc;
    }
    __syncthreads();

    if (tid < NC * NL) {
        int k = tid / NL, j = tid % NL;
        float acc = 0.0f;
#pragma unroll
        for (int n = 0; n < NC; n++)
            acc = fmaf(TcS[k][n], PS[n][j], acc);
        acc *= (2.0f / (float)NC) * (2.0f / (float)NL);
        if (j == 0) acc *= 0.5f;
        A2S[k][j] = acc;
    }
    __syncthreads();

    if (tid < NL) {
        int j = tid;
        float D[NC];
        D[NC - 1] = 0.0f;
        D[NC - 2] = (2.0f * (float)(NC - 1)) * A2S[NC - 1][j];
#pragma unroll
        for (int k = NC - 3; k >= 0; --k)
            D[k] = fmaf(2.0f * (float)(k + 1), A2S[k + 1][j], D[k + 2]);
#pragma unroll
        for (int k = 0; k < NC; k++)
            gD2[k * NL + j] = D[k] * (0.5f * INV_HALFW);
    }
}

// ---------------------------------------------------------------------------
// Packed Gamma: even/odd split Clenshaw.
// ---------------------------------------------------------------------------
__device__ __forceinline__ f2 gamma2(f2 c2, const f2 (&D)[NC], f2 h0,
                                     f2 invhP, f2 coffP, f2 m1P) {
    f2 yP = fma2_(c2, invhP, coffP);
    f2 tw = add2_(yP, yP);
    f2 zP = fma2_(tw, yP, m1P);        // z = 2y^2 - 1
    f2 z2P = add2_(zP, zP);
    f2 e1 = 0ULL, e2 = 0ULL;
#pragma unroll
    for (int m = 9; m >= 1; --m) {
        f2 u = fma2_(z2P, e1, fma2_(e2, m1P, D[2 * m]));
        e2 = e1; e1 = u;
    }
    f2 Se = fma2_(zP, e1, fma2_(e2, m1P, h0));        // h0 = 0.5*D[0] pair
    f2 o1 = 0ULL, o2 = 0ULL;
#pragma unroll
    for (int m = 8; m >= 1; --m) {
        f2 u = fma2_(z2P, o1, fma2_(o2, m1P, D[2 * m + 1]));
        o2 = o1; o1 = u;
    }
    f2 w1P = add2_(z2P, m1P);                         // W_1(z) = 2z - 1
    f2 So = fma2_(w1P, o1, fma2_(o2, m1P, D[1]));
    return fma2_(yP, So, Se);
}

// 10 packed Euler steps, returning final c pair (shooting probe).
__device__ __forceinline__ f2 integrate_c2(f2 cs2, f2 v2, const f2 (&D)[NC],
                                           f2 h0, f2 invhP, f2 coffP, f2 m1P,
                                           f2 dtP, f2 mdtP) {
    f2 c2 = cs2, vv2 = v2;
#pragma unroll 1
    for (int k = 0; k < 10; ++k) {
        f2 g2 = gamma2(c2, D, h0, invhP, coffP, m1P);
        f2 cn = fma2_(vv2, dtP, c2);
        f2 t = mul2_(g2, vv2);
        t = mul2_(t, vv2);
        vv2 = fma2_(t, mdtP, vv2);
        c2 = cn;
    }
    return c2;
}

// ---------------------------------------------------------------------------
// Main kernel: 2 elements per thread, packed; natural regs (3 blocks/SM).
// ---------------------------------------------------------------------------
__global__ void __launch_bounds__(128, 3) geo_main_kernel(
    const float* __restrict__ c_source, const float* __restrict__ c_target,
    const float* __restrict__ lamv, const float* __restrict__ A_source,
    const float* __restrict__ sW1, const float* __restrict__ sb1,
    const float* __restrict__ sW2, const float* __restrict__ sb2,
    float* __restrict__ out, int n, int half)
{
    __shared__ f2 D2dup[NC * NL];     // coefficients duplicated into both lanes
    __shared__ float fwc[HS], fwv[HS], fwA[HS], fwo[HS];  // uniform flow weights
    for (int k = threadIdx.x; k < NC * NL; k += blockDim.x) {
        float w = gD2[k];
        D2dup[k] = pk2(w, w);
    }
    if (threadIdx.x < HS) {
        int j = threadIdx.x;
        fwc[j] = sW1[j] * TWO_LOG2E_F;
        fwv[j] = sW1[HS + j] * TWO_LOG2E_F;
        fwA[j] = sW1[3 * HS + j] * TWO_LOG2E_F;
        fwo[j] = sW2[j];
    }
    __syncthreads();

    int t = blockIdx.x * blockDim.x + threadIdx.x;
    if (t >= half) return;
    int i0 = t, i1 = t + half;
    bool has1 = (i1 < n);
    int i1s = has1 ? i1 : i0;

    float cs0 = c_source[i0], ct0 = c_target[i0], lam0 = lamv[i0];
    float cs1 = c_source[i1s], ct1 = c_target[i1s], lam1 = lamv[i1s];

    const f2 m1P   = pk2(-1.0f, -1.0f);
    const f2 dtP   = pk2(DT, DT);
    const f2 mdtP  = pk2(-DT, -DT);
    const f2 invhP = pk2(INV_HALFW, INV_HALFW);
    const f2 coffP = pk2(-C_CENTER * INV_HALFW, -C_CENTER * INV_HALFW);

    // lam Chebyshev basis (packed) + contraction -> packed series Dc
    float yl0 = fminf(fmaxf(fmaf(2.0f, lam0, -1.0f), -1.0f), 1.0f);
    float yl1 = fminf(fmaxf(fmaf(2.0f, lam1, -1.0f), -1.0f), 1.0f);
    f2 ylP = pk2(yl0, yl1);
    f2 y2lP = add2_(ylP, ylP);
    f2 Tl[NL];
    Tl[0] = pk2(1.0f, 1.0f);
    Tl[1] = ylP;
#pragma unroll
    for (int j = 2; j < NL; j++)
        Tl[j] = fma2_(y2lP, Tl[j - 1], mul2_(Tl[j - 2], m1P));

    f2 Dc[NC];
#pragma unroll
    for (int k = 0; k < NC; k++) {
        f2 acc = D2dup[k * NL];        // Tl[0] == 1
#pragma unroll
        for (int j = 1; j < NL; j++)
            acc = fma2_(D2dup[k * NL + j], Tl[j], acc);
        Dc[k] = acc;
    }
    f2 h0 = mul2_(Dc[0], pk2(0.5f, 0.5f));

    // ---- shooting: 2 exact Newton iterations + secant closure of 8 ----
    float v0 = ct0 - cs0, v1 = ct1 - cs1;
    f2 cs2 = pk2(cs0, cs1);
    float va0 = 0.f, ra0 = 0.f, vb0 = 0.f, rb0 = 0.f;
    float va1 = 0.f, ra1 = 0.f, vb1 = 0.f, rb1 = 0.f;
#pragma unroll 1
    for (int it = 0; it < 2; ++it) {
        f2 cf2 = integrate_c2(cs2, pk2(v0, v1), Dc, h0, invhP, coffP, m1P, dtP, mdtP);
        float cf0, cf1;
        upk2(cf0, cf1, cf2);
        float r0 = cf0 - ct0, r1 = cf1 - ct1;
        if (it == 0) { va0 = v0; ra0 = r0; va1 = v1; ra1 = r1; }
        if (it == 1) { vb0 = v0; rb0 = r0; vb1 = v1; rb1 = r1; }
        v0 = v0 - 0.5f * r0;
        v1 = v1 - 0.5f * r1;
    }
    // v = v2.  Model iterations 2..9: r_k = q^{k-1} r1, so
    // v10 = v2 - 0.5 * r1 * q * (1 + q + ... + q^7).
    {
        float db = vb0 - va0;
        float beta = (fabsf(db) > 1e-12f) ? __fdividef(rb0 - ra0, db) : 1.0f;
        float q = fminf(fmaxf(1.0f - 0.5f * beta, 0.0f), 0.9f);
        float S = 1.0f;
#pragma unroll
        for (int j = 0; j < 7; j++) S = fmaf(q, S, 1.0f);   // 1+q+...+q^7
        v0 = v0 - 0.5f * rb0 * q * S;
    }
    {
        float db = vb1 - va1;
        float beta = (fabsf(db) > 1e-12f) ? __fdividef(rb1 - ra1, db) : 1.0f;
        float q = fminf(fmaxf(1.0f - 0.5f * beta, 0.0f), 0.9f);
        float S = 1.0f;
#pragma unroll
        for (int j = 0; j < 7; j++) S = fmaf(q, S, 1.0f);
        v1 = v1 - 0.5f * rb1 * q * S;
    }

    // ---- final integrate: packed Gamma/steps + scalar x2 flow MLP ----
    float sbp0[HS], sbp1[HS];
#pragma unroll
    for (int j = 0; j < HS; j++) {
        sbp0[j] = fmaf(lam0, sW1[2 * HS + j], sb1[j]) * TWO_LOG2E_F;
        sbp1[j] = fmaf(lam1, sW1[2 * HS + j], sb1[j]) * TWO_LOG2E_F;
    }
    float sb2s = sb2[0];

    float A0 = A_source[i0], A1 = A_source[i1s];
    f2 c2 = cs2;
    f2 v2 = pk2(v0, v1);
#pragma unroll 1
    for (int k = 0; k < 10; ++k) {
        f2 g2 = gamma2(c2, Dc, h0, invhP, coffP, m1P);
        float cc0, cc1, vv0, vv1;
        upk2(cc0, cc1, c2);
        upk2(vv0, vv1, v2);
        float acc0 = sb2s, acc1 = sb2s;
#pragma unroll
        for (int j = 0; j < HS; j++) {
            float wc = fwc[j], wv = fwv[j], wA = fwA[j], wo = fwo[j];
            float a0 = fmaf(cc0, wc, sbp0[j]);
            a0 = fmaf(vv0, wv, a0);
            a0 = fmaf(A0, wA, a0);
            acc0 = fmaf(tanh_pre(a0), wo, acc0);
            float a1 = fmaf(cc1, wc, sbp1[j]);
            a1 = fmaf(vv1, wv, a1);
            a1 = fmaf(A1, wA, a1);
            acc1 = fmaf(tanh_pre(a1), wo, acc1);
        }
        c2 = fma2_(v2, dtP, c2);
        f2 tt = mul2_(g2, v2);
        tt = mul2_(tt, v2);
        v2 = fma2_(tt, mdtP, v2);
        A0 = fmaf(acc0, DT, A0);
        A1 = fmaf(acc1, DT, A1);
    }
    out[i0] = A0;
    if (has1) out[i1] = A1;
}

extern "C" void kernel_launch(void* const* d_in, const int* in_sizes, int n_in,
                              void* d_out, int out_size)
{
    const float* c_source = (const float*)d_in[0];
    const float* c_target = (const float*)d_in[1];
    const float* lam      = (const float*)d_in[2];
    const float* A_source = (const float*)d_in[3];
    const float* mW1 = (const float*)d_in[4];
    const float* mb1 = (const float*)d_in[5];
    const float* mW2 = (const float*)d_in[6];
    const float* mb2 = (const float*)d_in[7];
    const float* mW3 = (const float*)d_in[8];
    const float* mb3 = (const float*)d_in[9];
    const float* sW1 = (const float*)d_in[10];
    const float* sb1 = (const float*)d_in[11];
    const float* sW2 = (const float*)d_in[12];
    const float* sb2 = (const float*)d_in[13];
    float* out = (float*)d_out;

    int n = in_sizes[0];
    int half = (n + 1) / 2;
    int block = 128;
    int grid = (half + block - 1) / block;

    setup_kernel<<<1, 384>>>(mW1, mb1, mW2, mb2, mW3, mb3);
    geo_main_kernel<<<grid, block>>>(c_source, c_target, lam, A_source,
                                     sW1, sb1, sW2, sb2, out, n, half);
}